// round 16
// baseline (speedup 1.0000x reference)
#include <cuda_runtime.h>

#define BDIM 512
#define LL   2048
#define CC   12
#define NDIL 8
#define KK   8
#define GG   32
#define NCP  6

#define SCAT_OFF (2 * CC * LL)                 // 49152 floats
#define SMEM_FLOATS (SCAT_OFF + 16 * 256)      // + per-warp max columns = 53248 floats

typedef unsigned long long u64;
typedef unsigned int u32;

__device__ __forceinline__ int swz(int x){ return x ^ (((x>>5)^(x>>10))&31); }

__device__ __forceinline__ u64 pack2(float lo, float hi){
  u64 r; asm("mov.b64 %0, {%1,%2};" : "=l"(r) : "f"(lo), "f"(hi)); return r;
}
__device__ __forceinline__ u64 dup2(float v){
  u64 r; asm("mov.b64 %0, {%1,%1};" : "=l"(r) : "f"(v)); return r;
}
__device__ __forceinline__ void unpack2(u64 v, float& lo, float& hi){
  asm("mov.b64 {%0,%1}, %2;" : "=f"(lo), "=f"(hi) : "l"(v));
}
__device__ __forceinline__ u64 ffma2(u64 a, u64 b, u64 c){
  u64 r; asm("fma.rn.f32x2 %0, %1, %2, %3;" : "=l"(r) : "l"(a), "l"(b), "l"(c)); return r;
}
__device__ __forceinline__ u64 fmul2(u64 a, u64 b){
  u64 r; asm("mul.rn.f32x2 %0, %1, %2;" : "=l"(r) : "l"(a), "l"(b)); return r;
}
// embed k into low 3 mantissa bits: one LOP3 (R8-proven)
__device__ __forceinline__ float embed(float v, int k){
  u32 b = (__float_as_uint(v) & ~7u) | (u32)k;
  return __uint_as_float(b);
}

// one summed tap; jt valid iff 0 <= jt < P (else 0; wrapped addr harmless)
template<int DI>
__device__ __forceinline__ float tap(const float* __restrict__ sm, const int ro[6],
                                     int phase, int jt){
  constexpr int d = 1 << DI;
  constexpr int P = LL >> DI;
  int x = (phase + jt * d) & (LL - 1);
  int a = swz(x);
  float s = (sm[ro[0]+a] + sm[ro[1]+a]) + (sm[ro[2]+a] + sm[ro[3]+a])
          + (sm[ro[4]+a] + sm[ro[5]+a]);
  return ((unsigned)jt < (unsigned)P) ? s : 0.0f;
}

// 8 dots (rotating window), index-embedded max/min tournament (R8-proven).
__device__ __forceinline__ void dots_mm(const u64 pk[36], const u64 w2[9], int rot,
                                        float& m, float& n){
  u64 b0 = w2[rot % 9];
  u64 a0 = fmul2(pk[0],  b0), a1 = fmul2(pk[9],  b0),
      a2 = fmul2(pk[18], b0), a3 = fmul2(pk[27], b0);
  #pragma unroll
  for (int t = 1; t < 9; ++t){
    u64 wt = w2[(rot + t) % 9];
    a0 = ffma2(pk[t],      wt, a0);
    a1 = ffma2(pk[9 + t],  wt, a1);
    a2 = ffma2(pk[18 + t], wt, a2);
    a3 = ffma2(pk[27 + t], wt, a3);
  }
  float v0, v1, v2, v3, v4, v5, v6, v7;
  unpack2(a0, v0, v1); unpack2(a1, v2, v3);
  unpack2(a2, v4, v5); unpack2(a3, v6, v7);

  float e0 = embed(v0, 0), e1 = embed(v1, 1);
  float e2 = embed(v2, 2), e3 = embed(v3, 3);
  float e4 = embed(v4, 4), e5 = embed(v5, 5);
  float e6 = embed(v6, 6), e7 = embed(v7, 7);

  m = fmaxf(fmaxf(fmaxf(e0, e1), fmaxf(e2, e3)),
            fmaxf(fmaxf(e4, e5), fmaxf(e6, e7)));
  n = fminf(fminf(fminf(e0, e1), fminf(e2, e3)),
            fminf(fminf(e4, e5), fminf(e6, e7)));
}

template<int DI>
__device__ __forceinline__ void run_di(const float* __restrict__ sm,
                                       float* __restrict__ scm,   // warp base (no lane)
                                       const float* __restrict__ W,
                                       const int*   __restrict__ I,
                                       float* __restrict__ out,
                                       int b, int warp, int lane)
{
  constexpr int d    = 1 << DI;
  constexpr int P    = LL >> DI;
  constexpr int logP = 11 - DI;
  constexpr int SEG  = (P < 64) ? P : 64;   // {64,...,64,32,16}
  constexpr int NSEG = 64 / SEG;
  constexpr int NB   = SEG / 9;             // full 9-position blocks
  constexpr int REM  = SEG - 9 * NB;        // static remainder

  float* const scml = scm + lane;           // lane folded once (saves IADD/pos)

  for (int it = 0; it < 4; ++it){
    const int task = warp * 4 + it;
    const int diff = task >> 5, g = task & 31;

    const int* Ip = I + ((DI * 2 + diff) * GG + g) * NCP;
    int ro[6];
    #pragma unroll
    for (int j = 0; j < NCP; ++j) ro[j] = diff * CC * LL + __ldg(Ip + j) * LL;

    const float* Wp = W + (size_t)((DI * 2 + diff) * (KK * GG) + g * KK) * 9;
    u64 pk[36];   // pk[j*9+t] = (w[2j][t], w[2j+1][t])
    #pragma unroll
    for (int j = 0; j < 4; ++j)
      #pragma unroll
      for (int t = 0; t < 9; ++t)
        pk[j * 9 + t] = pack2(__ldg(Wp + (2 * j) * 9 + t),
                              __ldg(Wp + (2 * j + 1) * 9 + t));

    // zero this warp's private max columns (lane-private, no sync needed)
    #pragma unroll
    for (int k = 0; k < KK; ++k) scml[k << 5] = 0.0f;
    u64 cnt = 0ull;   // 8x8-bit min-count fields (<=64 per field per task)

    #pragma unroll 1
    for (int sg = 0; sg < NSEG; ++sg){
      const int q     = lane * 64 + sg * SEG;
      const int phase = q >> logP;
      const int j0    = q & (P - 1);

      u64 w2[9];
      #pragma unroll
      for (int t = 0; t < 9; ++t)
        w2[t] = dup2(tap<DI>(sm, ro, phase, j0 - 4 + t));

      int jb = j0 + 5;                      // next-tap base (hoisted +5)
      #pragma unroll 1
      for (int blk = 0; blk < NB; ++blk){
        #pragma unroll
        for (int u = 0; u < 9; ++u){
          float nv = tap<DI>(sm, ro, phase, jb + u);   // prefetch next tap
          float m, n;
          dots_mm(pk, w2, u, m, n);
          u32 mk = __float_as_uint(m) & 7u;
          u32 nk = __float_as_uint(n) & 7u;
          scml[mk << 5] += m;               // embedded value ≈ m (≤7 ulp)
          cnt += 1ull << (nk << 3);
          w2[u % 9] = dup2(nv);
        }
        jb += 9;
      }
      #pragma unroll
      for (int u = 0; u < REM; ++u){
        float nv = tap<DI>(sm, ro, phase, jb + u);
        float m, n;
        dots_mm(pk, w2, u, m, n);
        u32 mk = __float_as_uint(m) & 7u;
        u32 nk = __float_as_uint(n) & 7u;
        scml[mk << 5] += m;
        cnt += 1ull << (nk << 3);
        w2[u % 9] = dup2(nv);
      }
    }

    // diff stream Lout = 2047: subtract phantom output position l = 2047
    // (q = 2047 -> lane 31, phase = d-1, j = P-1; bitwise-identical recompute -> exact cancel)
    if (diff && lane == 31){
      u64 w9[9];
      #pragma unroll
      for (int t = 0; t < 9; ++t)
        w9[t] = dup2(tap<DI>(sm, ro, d - 1, P - 1 - 4 + t));
      float m, n;
      dots_mm(pk, w9, 0, m, n);
      u32 mk = __float_as_uint(m) & 7u;
      u32 nk = __float_as_uint(n) & 7u;
      scml[mk << 5] -= m;
      cnt -= 1ull << (nk << 3);
    }

    // cross-lane reduction from smem columns + register counters, then write
    float* o = out + (size_t)b * (NDIL * 2 * 2 * GG * KK)
                   + ((DI * 2 + diff) * 2) * (GG * KK) + g * KK;
    #pragma unroll
    for (int k = 0; k < KK; ++k){
      float vm = scml[k << 5];
      float vn = (float)((cnt >> (k << 3)) & 0xffull);
      #pragma unroll
      for (int off = 16; off > 0; off >>= 1){
        vm += __shfl_xor_sync(0xffffffffu, vm, off);
        vn += __shfl_xor_sync(0xffffffffu, vn, off);
      }
      if (lane == 0){
        o[k]           = vm;
        o[GG * KK + k] = vn;
      }
    }
  }
}

__global__ __launch_bounds__(BDIM, 1)
void hydra_kernel(const float* __restrict__ X,
                  const float* __restrict__ W,
                  const int*   __restrict__ I,
                  float* __restrict__ out)
{
  extern __shared__ float sm[];  // X (swz) | diff (diff[2047]=0) | per-warp max columns

  const int di = blockIdx.x;
  const int b  = blockIdx.y;
  const int tid = threadIdx.x;

  const float* Xb = X + (size_t)b * CC * LL;

  for (int i = tid; i < CC * LL; i += BDIM){
    int l = i & (LL - 1);
    float v  = Xb[i];
    float nv = (l < LL - 1) ? Xb[i + 1] : v;
    int a = swz(l);
    int c = i >> 11;
    sm[c * LL + a]           = v;
    sm[CC * LL + c * LL + a] = nv - v;
  }
  __syncthreads();

  const int warp = tid >> 5, lane = tid & 31;
  float* scm = sm + SCAT_OFF + warp * 256;

  switch (di){
    case 0: run_di<0>(sm, scm, W, I, out, b, warp, lane); break;
    case 1: run_di<1>(sm, scm, W, I, out, b, warp, lane); break;
    case 2: run_di<2>(sm, scm, W, I, out, b, warp, lane); break;
    case 3: run_di<3>(sm, scm, W, I, out, b, warp, lane); break;
    case 4: run_di<4>(sm, scm, W, I, out, b, warp, lane); break;
    case 5: run_di<5>(sm, scm, W, I, out, b, warp, lane); break;
    case 6: run_di<6>(sm, scm, W, I, out, b, warp, lane); break;
    default: run_di<7>(sm, scm, W, I, out, b, warp, lane); break;
  }
}

extern "C" void kernel_launch(void* const* d_in, const int* in_sizes, int n_in,
                              void* d_out, int out_size)
{
  const float* X   = (const float*)d_in[0];   // [B, 12, 2048] f32
  const float* W   = (const float*)d_in[1];   // [8, 2, 256, 1, 9] f32
  const int*   I   = (const int*)  d_in[2];   // [8, 2, 32, 6] i32
  float*       out = (float*)d_out;           // [B, 8192] f32

  const int B = in_sizes[0] / (CC * LL);
  const size_t smem = (size_t)SMEM_FLOATS * sizeof(float);   // 212992 B

  cudaFuncSetAttribute(hydra_kernel,
                       cudaFuncAttributeMaxDynamicSharedMemorySize, (int)smem);

  dim3 grid(NDIL, B);
  hydra_kernel<<<grid, BDIM, smem>>>(X, W, I, out);
}

// round 17
// speedup vs baseline: 1.0125x; 1.0125x over previous
#include <cuda_runtime.h>

#define BDIM 512
#define LL   2048
#define CC   12
#define NDIL 8
#define KK   8
#define GG   32
#define NCP  6

#define SCAT_OFF (2 * CC * LL)                        // 49152 floats
#define SMEM_FLOATS (SCAT_OFF + 16 * KK * 32 * 2)     // 57344 floats = 229376 B

typedef unsigned long long u64;
typedef unsigned int u32;

__device__ __forceinline__ int swz(int x){ return x ^ (((x>>5)^(x>>10))&31); }

__device__ __forceinline__ u64 pack2(float lo, float hi){
  u64 r; asm("mov.b64 %0, {%1,%2};" : "=l"(r) : "f"(lo), "f"(hi)); return r;
}
__device__ __forceinline__ u64 dup2(float v){
  u64 r; asm("mov.b64 %0, {%1,%1};" : "=l"(r) : "f"(v)); return r;
}
__device__ __forceinline__ void unpack2(u64 v, float& lo, float& hi){
  asm("mov.b64 {%0,%1}, %2;" : "=f"(lo), "=f"(hi) : "l"(v));
}
__device__ __forceinline__ u64 ffma2(u64 a, u64 b, u64 c){
  u64 r; asm("fma.rn.f32x2 %0, %1, %2, %3;" : "=l"(r) : "l"(a), "l"(b), "l"(c)); return r;
}
__device__ __forceinline__ u64 fmul2(u64 a, u64 b){
  u64 r; asm("mul.rn.f32x2 %0, %1, %2;" : "=l"(r) : "l"(a), "l"(b)); return r;
}
// embed k into low 3 mantissa bits: one LOP3
__device__ __forceinline__ float embed(float v, int k){
  u32 b = (__float_as_uint(v) & ~7u) | (u32)k;
  return __uint_as_float(b);
}

// one summed tap; jt is the tap's index in output space, valid iff 0 <= jt < P
template<int DI>
__device__ __forceinline__ float tap(const float* __restrict__ sm, const int ro[6],
                                     int phase, int jt){
  constexpr int d = 1 << DI;
  constexpr int P = LL >> DI;
  int x = (phase + jt * d) & (LL - 1);
  int a = swz(x);
  float s = (sm[ro[0]+a] + sm[ro[1]+a]) + (sm[ro[2]+a] + sm[ro[3]+a])
          + (sm[ro[4]+a] + sm[ro[5]+a]);
  return ((unsigned)jt < (unsigned)P) ? s : 0.0f;
}

// 8 dots (rotating window), index-embedded max/min tournament.
// m/n carry the winning k in their low 3 bits.
__device__ __forceinline__ void dots_mm(const u64 pk[36], const u64 w2[9], int rot,
                                        float& m, float& n){
  u64 b0 = w2[rot % 9];
  u64 a0 = fmul2(pk[0],  b0), a1 = fmul2(pk[9],  b0),
      a2 = fmul2(pk[18], b0), a3 = fmul2(pk[27], b0);
  #pragma unroll
  for (int t = 1; t < 9; ++t){
    u64 wt = w2[(rot + t) % 9];
    a0 = ffma2(pk[t],      wt, a0);
    a1 = ffma2(pk[9 + t],  wt, a1);
    a2 = ffma2(pk[18 + t], wt, a2);
    a3 = ffma2(pk[27 + t], wt, a3);
  }
  float a8[8];
  unpack2(a0, a8[0], a8[1]); unpack2(a1, a8[2], a8[3]);
  unpack2(a2, a8[4], a8[5]); unpack2(a3, a8[6], a8[7]);

  float e0 = embed(a8[0], 0), e1 = embed(a8[1], 1);
  float e2 = embed(a8[2], 2), e3 = embed(a8[3], 3);
  float e4 = embed(a8[4], 4), e5 = embed(a8[5], 5);
  float e6 = embed(a8[6], 6), e7 = embed(a8[7], 7);

  m = fmaxf(fmaxf(fmaxf(e0, e1), fmaxf(e2, e3)),
            fmaxf(fmaxf(e4, e5), fmaxf(e6, e7)));
  n = fminf(fminf(fminf(e0, e1), fminf(e2, e3)),
            fminf(fminf(e4, e5), fminf(e6, e7)));
}

template<int DI>
__device__ __forceinline__ void run_di(const float* __restrict__ sm,
                                       float* __restrict__ scm,
                                       float* __restrict__ scn,
                                       const float* __restrict__ W,
                                       const int*   __restrict__ I,
                                       float* __restrict__ out,
                                       int b, int warp, int lane)
{
  constexpr int d    = 1 << DI;
  constexpr int P    = LL >> DI;
  constexpr int logP = 11 - DI;
  constexpr int SEG  = (P < 64) ? P : 64;   // {64,...,64,32,16}
  constexpr int NSEG = 64 / SEG;
  constexpr int NB   = SEG / 9;             // full 9-position blocks
  constexpr int REM  = SEG - 9 * NB;        // static remainder

  for (int it = 0; it < 4; ++it){
    const int task = warp * 4 + it;
    const int diff = task >> 5, g = task & 31;

    const int* Ip = I + ((DI * 2 + diff) * GG + g) * NCP;
    int ro[6];
    #pragma unroll
    for (int j = 0; j < NCP; ++j) ro[j] = diff * CC * LL + __ldg(Ip + j) * LL;

    const float* Wp = W + (size_t)((DI * 2 + diff) * (KK * GG) + g * KK) * 9;
    u64 pk[36];   // pk[j*9+t] = (w[2j][t], w[2j+1][t])
    #pragma unroll
    for (int j = 0; j < 4; ++j)
      #pragma unroll
      for (int t = 0; t < 9; ++t)
        pk[j * 9 + t] = pack2(__ldg(Wp + (2 * j) * 9 + t),
                              __ldg(Wp + (2 * j + 1) * 9 + t));

    // zero this warp's private scatter columns (lane-private, no sync needed)
    #pragma unroll
    for (int k = 0; k < KK; ++k){
      scm[(k << 5) + lane] = 0.0f;
      scn[(k << 5) + lane] = 0.0f;
    }

    #pragma unroll 1
    for (int sg = 0; sg < NSEG; ++sg){
      const int q     = lane * 64 + sg * SEG;
      const int phase = q >> logP;
      const int j0    = q & (P - 1);

      u64 w2[9];
      #pragma unroll
      for (int t = 0; t < 9; ++t)
        w2[t] = dup2(tap<DI>(sm, ro, phase, j0 - 4 + t));

      int jp = j0;
      #pragma unroll 1
      for (int blk = 0; blk < NB; ++blk){
        #pragma unroll
        for (int u = 0; u < 9; ++u){
          float nv = tap<DI>(sm, ro, phase, jp + u + 5);   // prefetch next tap
          float m, n;
          dots_mm(pk, w2, u, m, n);
          int mk = (int)(__float_as_uint(m) & 7u);
          int nk = (int)(__float_as_uint(n) & 7u);
          scm[(mk << 5) + lane] += m;       // embedded value ≈ m (≤7 ulp)
          scn[(nk << 5) + lane] += 1.0f;
          w2[u % 9] = dup2(nv);
        }
        jp += 9;
      }
      #pragma unroll
      for (int u = 0; u < REM; ++u){
        float nv = tap<DI>(sm, ro, phase, jp + u + 5);
        float m, n;
        dots_mm(pk, w2, u, m, n);
        int mk = (int)(__float_as_uint(m) & 7u);
        int nk = (int)(__float_as_uint(n) & 7u);
        scm[(mk << 5) + lane] += m;
        scn[(nk << 5) + lane] += 1.0f;
        w2[u % 9] = dup2(nv);
      }
    }

    // diff stream Lout = 2047: subtract phantom output position l = 2047
    // (q = 2047 -> lane 31, phase = d-1, j = P-1; bitwise-identical recompute -> exact cancel)
    if (diff && lane == 31){
      u64 w9[9];
      #pragma unroll
      for (int t = 0; t < 9; ++t)
        w9[t] = dup2(tap<DI>(sm, ro, d - 1, P - 1 - 4 + t));
      float m, n;
      dots_mm(pk, w9, 0, m, n);
      int mk = (int)(__float_as_uint(m) & 7u);
      int nk = (int)(__float_as_uint(n) & 7u);
      scm[(mk << 5) + 31] -= m;
      scn[(nk << 5) + 31] -= 1.0f;
    }

    // cross-lane reduction from smem columns + write
    float* o = out + (size_t)b * (NDIL * 2 * 2 * GG * KK)
                   + ((DI * 2 + diff) * 2) * (GG * KK) + g * KK;
    #pragma unroll
    for (int k = 0; k < KK; ++k){
      float vm = scm[(k << 5) + lane];
      float vn = scn[(k << 5) + lane];
      #pragma unroll
      for (int off = 16; off > 0; off >>= 1){
        vm += __shfl_xor_sync(0xffffffffu, vm, off);
        vn += __shfl_xor_sync(0xffffffffu, vn, off);
      }
      if (lane == 0){
        o[k]           = vm;
        o[GG * KK + k] = vn;
      }
    }
  }
}

__global__ __launch_bounds__(BDIM, 1)
void hydra_kernel(const float* __restrict__ X,
                  const float* __restrict__ W,
                  const int*   __restrict__ I,
                  float* __restrict__ out)
{
  extern __shared__ float sm[];  // X (swz) | diff (diff[2047]=0) | scatter columns

  const int di = blockIdx.x;
  const int b  = blockIdx.y;
  const int tid = threadIdx.x;

  const float* Xb = X + (size_t)b * CC * LL;

  for (int i = tid; i < CC * LL; i += BDIM){
    int l = i & (LL - 1);
    float v  = Xb[i];
    float nv = (l < LL - 1) ? Xb[i + 1] : v;
    int a = swz(l);
    int c = i >> 11;
    sm[c * LL + a]           = v;
    sm[CC * LL + c * LL + a] = nv - v;
  }
  __syncthreads();

  const int warp = tid >> 5, lane = tid & 31;
  float* scm = sm + SCAT_OFF + warp * (KK * 32);
  float* scn = sm + SCAT_OFF + 16 * (KK * 32) + warp * (KK * 32);

  switch (di){
    case 0: run_di<0>(sm, scm, scn, W, I, out, b, warp, lane); break;
    case 1: run_di<1>(sm, scm, scn, W, I, out, b, warp, lane); break;
    case 2: run_di<2>(sm, scm, scn, W, I, out, b, warp, lane); break;
    case 3: run_di<3>(sm, scm, scn, W, I, out, b, warp, lane); break;
    case 4: run_di<4>(sm, scm, scn, W, I, out, b, warp, lane); break;
    case 5: run_di<5>(sm, scm, scn, W, I, out, b, warp, lane); break;
    case 6: run_di<6>(sm, scm, scn, W, I, out, b, warp, lane); break;
    default: run_di<7>(sm, scm, scn, W, I, out, b, warp, lane); break;
  }
}

extern "C" void kernel_launch(void* const* d_in, const int* in_sizes, int n_in,
                              void* d_out, int out_size)
{
  const float* X   = (const float*)d_in[0];   // [B, 12, 2048] f32
  const float* W   = (const float*)d_in[1];   // [8, 2, 256, 1, 9] f32
  const int*   I   = (const int*)  d_in[2];   // [8, 2, 32, 6] i32
  float*       out = (float*)d_out;           // [B, 8192] f32

  const int B = in_sizes[0] / (CC * LL);
  const size_t smem = (size_t)SMEM_FLOATS * sizeof(float);   // 229376 B

  cudaFuncSetAttribute(hydra_kernel,
                       cudaFuncAttributeMaxDynamicSharedMemorySize, (int)smem);

  dim3 grid(NDIL, B);
  hydra_kernel<<<grid, BDIM, smem>>>(X, W, I, out);
}